// round 1
// baseline (speedup 1.0000x reference)
#include <cuda_runtime.h>
#include <cstdint>
#include <cstddef>

#define Bx 32
#define Tt 64
#define Dd 1024
#define Hh 1024
#define Vv 32000
#define MX 100
#define BH (Bx*Hh)

// ---------------- device scratch (no allocations allowed) ----------------
__device__ float g_hs[(size_t)Tt*BH];   // teacher-forced hidden states [T][B][H]
__device__ float g_zeros[BH];
__device__ float g_ctf[BH];
__device__ float g_cgr[BH];
__device__ float g_hg0[BH];
__device__ float g_hg1[BH];
__device__ unsigned long long g_slots[64];  // two ping-pong buffers of 32

// ordered-float key: monotonic uint mapping of float
__device__ __forceinline__ unsigned int fkey(float f) {
    unsigned int u = __float_as_uint(f);
    return (u & 0x80000000u) ? ~u : (u | 0x80000000u);
}

__global__ void init_kernel() {
    int i = blockIdx.x * blockDim.x + threadIdx.x;
    if (i < BH) { g_zeros[i] = 0.f; g_ctf[i] = 0.f; g_cgr[i] = 0.f; }
}

// ---------------- fused LSTM cell step ----------------
// Computes z = x@Wx + h@Wh + b for all 4 gates, applies gate math, writes h_out, c.
// x is gathered from Wo via tokens (mode 0: int array, 1: GO=1 const, 2: decode argmax slots).
// grid: 128 blocks (8 hidden cols each), 256 threads.
__global__ void __launch_bounds__(256) lstm_cell(
    const float* __restrict__ Wx, const float* __restrict__ Wh,
    const float* __restrict__ bias, const float* __restrict__ Wo,
    const int* __restrict__ tok_src, int tok_stride, int mode,
    const unsigned long long* __restrict__ slots_in,
    unsigned long long* __restrict__ slots_reset,
    float* __restrict__ best_prev_out,
    const float* __restrict__ h_in, float* __restrict__ h_out,
    float* __restrict__ c)
{
    __shared__ float in_sh[64][32];
    __shared__ float gate_sh[32][33];
    __shared__ int tok_sh[32];

    int tid = threadIdx.x;
    if (tid < 32) {
        int tk;
        if (mode == 0) tk = tok_src[tid * tok_stride];
        else if (mode == 1) tk = 1;  // GO token
        else {
            unsigned long long p = slots_in[tid];
            tk = (int)(0xFFFFFFFFu - (unsigned int)(p & 0xFFFFFFFFull));
            if (blockIdx.x == 0 && best_prev_out) best_prev_out[tid] = (float)tk;
        }
        tok_sh[tid] = tk;
        if (blockIdx.x == 0 && slots_reset) slots_reset[tid] = 0ull;
    }
    __syncthreads();

    const int col   = tid & 31;      // (gate, j) pair
    const int g     = col >> 3;
    const int j     = col & 7;
    const int jbase = blockIdx.x * 8;
    const int wcol  = g * Hh + jbase + j;     // column in [4H]
    const int b0    = (tid >> 5) * 4;          // 4 batches per thread
    const int lb    = tid >> 3;                // loader batch
    const int q     = tid & 7;                 // loader chunk

    float acc0 = 0.f, acc1 = 0.f, acc2 = 0.f, acc3 = 0.f;

    #pragma unroll
    for (int ph = 0; ph < 2; ph++) {
        const float* W = ph ? Wh : Wx;
        for (int k0 = 0; k0 < 1024; k0 += 64) {
            const float* src = (ph == 0)
                ? (Wo + (size_t)tok_sh[lb] * Dd + k0 + q * 8)
                : (h_in + lb * Hh + k0 + q * 8);
            float4 v0 = *(const float4*)src;
            float4 v1 = *(const float4*)(src + 4);
            __syncthreads();  // previous chunk fully consumed
            int kk = q * 8;
            in_sh[kk+0][lb] = v0.x; in_sh[kk+1][lb] = v0.y;
            in_sh[kk+2][lb] = v0.z; in_sh[kk+3][lb] = v0.w;
            in_sh[kk+4][lb] = v1.x; in_sh[kk+5][lb] = v1.y;
            in_sh[kk+6][lb] = v1.z; in_sh[kk+7][lb] = v1.w;
            __syncthreads();
            const float* wp = W + (size_t)k0 * 4096 + wcol;
            #pragma unroll 8
            for (int k = 0; k < 64; k++) {
                float w = wp[(size_t)k * 4096];
                float4 xv = *(const float4*)&in_sh[k][b0];
                acc0 += xv.x * w; acc1 += xv.y * w;
                acc2 += xv.z * w; acc3 += xv.w * w;
            }
        }
    }
    __syncthreads();
    gate_sh[col][b0+0] = acc0; gate_sh[col][b0+1] = acc1;
    gate_sh[col][b0+2] = acc2; gate_sh[col][b0+3] = acc3;
    __syncthreads();

    {
        int jj = tid >> 5;        // 0..7
        int b  = tid & 31;        // batch
        int J  = jbase + jj;
        float zi = gate_sh[0*8 + jj][b] + bias[J];
        float zf = gate_sh[1*8 + jj][b] + bias[Hh + J];
        float zg = gate_sh[2*8 + jj][b] + bias[2*Hh + J];
        float zo = gate_sh[3*8 + jj][b] + bias[3*Hh + J];
        float cold = c[b * Hh + J];
        float fg = 1.f / (1.f + expf(-(zf + 1.f)));   // forget_bias = 1.0
        float ig = 1.f / (1.f + expf(-zi));
        float og = 1.f / (1.f + expf(-zo));
        float cn = fg * cold + ig * tanhf(zg);
        float hn = og * tanhf(cn);
        c[b * Hh + J] = cn;
        h_out[b * Hh + J] = hn;
    }
}

// ---------------- big teacher-forced logits GEMM ----------------
// C[2048,32000] = A[2048,1024] @ B[1024,32000], fp32, 128x128x8 double-buffered.
__global__ void __launch_bounds__(256, 2) gemm_logits(
    const float* __restrict__ A, const float* __restrict__ Bm, float* __restrict__ C)
{
    __shared__ float As[2][8][128];
    __shared__ float Bs[2][8][128];
    int tid = threadIdx.x;
    int nbase = blockIdx.x * 128;
    int mbase = blockIdx.y * 128;
    int tx = tid & 15, ty = tid >> 4;

    float acc[8][8];
    #pragma unroll
    for (int i = 0; i < 8; i++)
        #pragma unroll
        for (int jj = 0; jj < 8; jj++) acc[i][jj] = 0.f;

    int arow = tid >> 1, akq = (tid & 1) * 4;
    int bk = tid >> 5, bnq = (tid & 31) * 4;
    const float* Aptr = A + (size_t)(mbase + arow) * 1024 + akq;
    const float* Bptr = Bm + (size_t)bk * Vv + nbase + bnq;

    {
        float4 av = *(const float4*)Aptr;
        float4 bv = *(const float4*)Bptr;
        As[0][akq+0][arow] = av.x; As[0][akq+1][arow] = av.y;
        As[0][akq+2][arow] = av.z; As[0][akq+3][arow] = av.w;
        *(float4*)&Bs[0][bk][bnq] = bv;
    }
    __syncthreads();

    int buf = 0;
    for (int k0 = 0; k0 < 1024; k0 += 8) {
        float4 av2, bv2;
        bool has = (k0 + 8) < 1024;
        if (has) {
            av2 = *(const float4*)(Aptr + (k0 + 8));
            bv2 = *(const float4*)(Bptr + (size_t)(k0 + 8) * Vv);
        }
        #pragma unroll
        for (int kk = 0; kk < 8; kk++) {
            float4 a0 = *(const float4*)&As[buf][kk][ty*8];
            float4 a1 = *(const float4*)&As[buf][kk][ty*8 + 4];
            float4 c0 = *(const float4*)&Bs[buf][kk][tx*8];
            float4 c1 = *(const float4*)&Bs[buf][kk][tx*8 + 4];
            float ar[8] = {a0.x,a0.y,a0.z,a0.w,a1.x,a1.y,a1.z,a1.w};
            float br[8] = {c0.x,c0.y,c0.z,c0.w,c1.x,c1.y,c1.z,c1.w};
            #pragma unroll
            for (int i = 0; i < 8; i++)
                #pragma unroll
                for (int jj = 0; jj < 8; jj++)
                    acc[i][jj] += ar[i] * br[jj];
        }
        if (has) {
            int nb = buf ^ 1;
            As[nb][akq+0][arow] = av2.x; As[nb][akq+1][arow] = av2.y;
            As[nb][akq+2][arow] = av2.z; As[nb][akq+3][arow] = av2.w;
            *(float4*)&Bs[nb][bk][bnq] = bv2;
            __syncthreads();
            buf = nb;
        }
    }
    #pragma unroll
    for (int i = 0; i < 8; i++) {
        int row = mbase + ty * 8 + i;
        float* ptr = C + (size_t)row * Vv + nbase + tx * 8;
        float4 o0 = {acc[i][0], acc[i][1], acc[i][2], acc[i][3]};
        float4 o1 = {acc[i][4], acc[i][5], acc[i][6], acc[i][7]};
        *(float4*)ptr = o0;
        *(float4*)(ptr + 4) = o1;
    }
}

// ---------------- softmax over V per (t,b) row ----------------
__global__ void __launch_bounds__(256) softmax_kernel(
    const float* __restrict__ lg, float* __restrict__ pr)
{
    int row = blockIdx.x;
    const float4* src = (const float4*)(lg + (size_t)row * Vv);
    float4* dst = (float4*)(pr + (size_t)row * Vv);
    const int n4 = Vv / 4;
    int tid = threadIdx.x;

    __shared__ float red[8];
    __shared__ float s_max, s_sum;

    float m = -3.4e38f;
    for (int i = tid; i < n4; i += 256) {
        float4 v = src[i];
        m = fmaxf(m, fmaxf(fmaxf(v.x, v.y), fmaxf(v.z, v.w)));
    }
    #pragma unroll
    for (int o = 16; o; o >>= 1) m = fmaxf(m, __shfl_xor_sync(0xffffffffu, m, o));
    if ((tid & 31) == 0) red[tid >> 5] = m;
    __syncthreads();
    if (tid == 0) {
        float t = red[0];
        #pragma unroll
        for (int i = 1; i < 8; i++) t = fmaxf(t, red[i]);
        s_max = t;
    }
    __syncthreads();
    float rm = s_max;

    float s = 0.f;
    for (int i = tid; i < n4; i += 256) {
        float4 v = src[i];
        s += __expf(v.x - rm) + __expf(v.y - rm) + __expf(v.z - rm) + __expf(v.w - rm);
    }
    #pragma unroll
    for (int o = 16; o; o >>= 1) s += __shfl_xor_sync(0xffffffffu, s, o);
    if ((tid & 31) == 0) red[tid >> 5] = s;
    __syncthreads();
    if (tid == 0) {
        float t = 0.f;
        #pragma unroll
        for (int i = 0; i < 8; i++) t += red[i];
        s_sum = t;
    }
    __syncthreads();
    float inv = 1.f / s_sum;

    for (int i = tid; i < n4; i += 256) {
        float4 v = src[i];
        float4 o;
        o.x = __expf(v.x - rm) * inv; o.y = __expf(v.y - rm) * inv;
        o.z = __expf(v.z - rm) * inv; o.w = __expf(v.w - rm) * inv;
        dst[i] = o;
    }
}

// ---------------- greedy projection lg = h@Wp + block argmax ----------------
// grid 500 blocks x 64 cols; per-block packed max -> atomicMax into 32 slots.
__global__ void __launch_bounds__(256, 3) proj_argmax(
    const float* __restrict__ h, const float* __restrict__ Wp,
    unsigned long long* __restrict__ slots)
{
    __shared__ float in_sh[128][32];
    __shared__ unsigned long long wred[8][8];
    int tid = threadIdx.x;
    int col = tid & 63;
    int b0 = (tid >> 6) * 8;
    int colg = blockIdx.x * 64 + col;
    int lb = tid >> 3, q = tid & 7;

    float acc[8];
    #pragma unroll
    for (int i = 0; i < 8; i++) acc[i] = 0.f;

    for (int k0 = 0; k0 < 1024; k0 += 128) {
        const float* src = h + lb * Hh + k0 + q * 16;
        float4 v0 = *(const float4*)src;
        float4 v1 = *(const float4*)(src + 4);
        float4 v2 = *(const float4*)(src + 8);
        float4 v3 = *(const float4*)(src + 12);
        __syncthreads();
        int kk = q * 16;
        in_sh[kk+ 0][lb] = v0.x; in_sh[kk+ 1][lb] = v0.y; in_sh[kk+ 2][lb] = v0.z; in_sh[kk+ 3][lb] = v0.w;
        in_sh[kk+ 4][lb] = v1.x; in_sh[kk+ 5][lb] = v1.y; in_sh[kk+ 6][lb] = v1.z; in_sh[kk+ 7][lb] = v1.w;
        in_sh[kk+ 8][lb] = v2.x; in_sh[kk+ 9][lb] = v2.y; in_sh[kk+10][lb] = v2.z; in_sh[kk+11][lb] = v2.w;
        in_sh[kk+12][lb] = v3.x; in_sh[kk+13][lb] = v3.y; in_sh[kk+14][lb] = v3.z; in_sh[kk+15][lb] = v3.w;
        __syncthreads();
        const float* wp = Wp + (size_t)k0 * Vv + colg;
        #pragma unroll 8
        for (int k = 0; k < 128; k++) {
            float w = wp[(size_t)k * Vv];
            float4 x0 = *(const float4*)&in_sh[k][b0];
            float4 x1 = *(const float4*)&in_sh[k][b0 + 4];
            acc[0] += x0.x * w; acc[1] += x0.y * w; acc[2] += x0.z * w; acc[3] += x0.w * w;
            acc[4] += x1.x * w; acc[5] += x1.y * w; acc[6] += x1.z * w; acc[7] += x1.w * w;
        }
    }

    // pack (value, inverted index) so max => max value, ties => smallest index (jnp.argmax)
    unsigned long long pk[8];
    #pragma unroll
    for (int i = 0; i < 8; i++)
        pk[i] = ((unsigned long long)fkey(acc[i]) << 32)
              | (unsigned long long)(0xFFFFFFFFu - (unsigned int)colg);
    #pragma unroll
    for (int o = 16; o; o >>= 1) {
        #pragma unroll
        for (int i = 0; i < 8; i++) {
            unsigned long long other = __shfl_xor_sync(0xffffffffu, pk[i], o);
            if (other > pk[i]) pk[i] = other;
        }
    }
    int w = tid >> 5;
    if ((tid & 31) == 0) {
        #pragma unroll
        for (int i = 0; i < 8; i++) wred[w][i] = pk[i];
    }
    __syncthreads();
    if (tid < 32) {
        int b = tid, bg = b >> 3, bi = b & 7;
        unsigned long long m0 = wred[bg * 2][bi];
        unsigned long long m1 = wred[bg * 2 + 1][bi];
        if (m1 > m0) m0 = m1;
        atomicMax(&slots[b], m0);
    }
}

__global__ void final_writer(const unsigned long long* __restrict__ slots,
                             float* __restrict__ best_out)
{
    int b = threadIdx.x;
    if (b < 32) {
        unsigned long long p = slots[b];
        best_out[b] = (float)(0xFFFFFFFFu - (unsigned int)(p & 0xFFFFFFFFull));
    }
}

// ---------------- host orchestration (graph-capturable) ----------------
extern "C" void kernel_launch(void* const* d_in, const int* in_sizes, int n_in,
                              void* d_out, int out_size)
{
    (void)in_sizes; (void)n_in; (void)out_size;
    const int*   tgt  = (const int*)d_in[0];
    const float* Wo   = (const float*)d_in[1];
    const float* Wx   = (const float*)d_in[2];
    const float* Wh   = (const float*)d_in[3];
    const float* bias = (const float*)d_in[4];
    const float* Wp   = (const float*)d_in[5];

    float* out = (float*)d_out;
    float* out_logits = out;
    float* out_probs  = out + (size_t)Tt * Bx * Vv;
    float* out_best   = out + (size_t)2 * Tt * Bx * Vv;

    float *hs, *zeros, *ctf, *cgr, *hg0, *hg1;
    unsigned long long* slots;
    cudaGetSymbolAddress((void**)&hs,    g_hs);
    cudaGetSymbolAddress((void**)&zeros, g_zeros);
    cudaGetSymbolAddress((void**)&ctf,   g_ctf);
    cudaGetSymbolAddress((void**)&cgr,   g_cgr);
    cudaGetSymbolAddress((void**)&hg0,   g_hg0);
    cudaGetSymbolAddress((void**)&hg1,   g_hg1);
    cudaGetSymbolAddress((void**)&slots, g_slots);

    init_kernel<<<(BH + 1023) / 1024, 1024>>>();

    // ---- teacher-forced scan: h_t stored into g_hs[t] ----
    for (int t = 0; t < Tt; t++) {
        lstm_cell<<<128, 256>>>(
            Wx, Wh, bias, Wo,
            tgt + t, Tt, /*mode=*/0,
            nullptr, nullptr, nullptr,
            (t == 0) ? zeros : hs + (size_t)(t - 1) * BH,
            hs + (size_t)t * BH, ctf);
    }

    // ---- logits + softmax ----
    gemm_logits<<<dim3(Vv / 128, (Tt * Bx) / 128), 256>>>(hs, Wp, out_logits);
    softmax_kernel<<<Tt * Bx, 256>>>(out_logits, out_probs);

    // ---- greedy decode ----
    for (int s = 0; s < MX; s++) {
        const float* hi = (s == 0) ? zeros : (((s - 1) & 1) ? hg1 : hg0);
        float* ho = (s & 1) ? hg1 : hg0;
        lstm_cell<<<128, 256>>>(
            Wx, Wh, bias, Wo,
            nullptr, 0, (s == 0) ? 1 : 2,
            (s == 0) ? nullptr : slots + ((s - 1) & 1) * 32,
            slots + (s & 1) * 32,
            (s == 0) ? nullptr : out_best + (size_t)(s - 1) * 32,
            hi, ho, cgr);
        proj_argmax<<<Vv / 64, 256>>>(ho, Wp, slots + (s & 1) * 32);
    }
    final_writer<<<1, 32>>>(slots + ((MX - 1) & 1) * 32,
                            out_best + (size_t)(MX - 1) * 32);
}

// round 2
// speedup vs baseline: 3.3155x; 3.3155x over previous
#include <cuda_runtime.h>
#include <cstdint>
#include <cstddef>

#define Bx 32
#define Tt 64
#define Dd 1024
#define Hh 1024
#define Vv 32000
#define MX 100
#define BH (Bx*Hh)

typedef unsigned long long ull;

// ---------------- device scratch (no allocations allowed) ----------------
__device__ float g_hs[(size_t)Tt*BH];   // teacher-forced hidden states [T][B][H]
__device__ float g_zeros[BH];
__device__ float g_ctf[BH];
__device__ float g_cgr[BH];
__device__ float g_hg0[BH];
__device__ float g_hg1[BH];
__device__ ull g_slots[64];  // two ping-pong buffers of 32

// ---------------- packed fp32x2 helpers (Blackwell FFMA2) ----------------
__device__ __forceinline__ ull fma2(ull a, ull b, ull c) {
    ull d;
    asm("fma.rn.f32x2 %0, %1, %2, %3;" : "=l"(d) : "l"(a), "l"(b), "l"(c));
    return d;
}
__device__ __forceinline__ ull pack2(float lo, float hi) {
    ull d; asm("mov.b64 %0, {%1, %2};" : "=l"(d) : "f"(lo), "f"(hi)); return d;
}
__device__ __forceinline__ float lo2(ull v) { return __uint_as_float((unsigned int)(v & 0xFFFFFFFFull)); }
__device__ __forceinline__ float hi2(ull v) { return __uint_as_float((unsigned int)(v >> 32)); }

// ordered-float key: monotonic uint mapping of float
__device__ __forceinline__ unsigned int fkey(float f) {
    unsigned int u = __float_as_uint(f);
    return (u & 0x80000000u) ? ~u : (u | 0x80000000u);
}

__global__ void init_kernel() {
    int i = blockIdx.x * blockDim.x + threadIdx.x;
    if (i < BH) { g_zeros[i] = 0.f; g_ctf[i] = 0.f; g_cgr[i] = 0.f; }
}

// ---------------- fused LSTM cell step (smem-staged, double-buffered, FFMA2) ----
// grid 128 blocks; block bid handles hidden cols j in [bid*8, bid*8+8) x 4 gates
// = 32 columns x 32 batches. K = 2048 (1024 from Wo-gather, 1024 from h_in),
// chunked 32 k at a time through shared memory.
__global__ void __launch_bounds__(256) lstm_cell(
    const float* __restrict__ Wx, const float* __restrict__ Wh,
    const float* __restrict__ bias, const float* __restrict__ Wo,
    const int* __restrict__ tok_src, int tok_stride, int mode,
    const ull* __restrict__ slots_in,
    ull* __restrict__ slots_reset,
    float* __restrict__ best_prev_out,
    const float* __restrict__ h_in, float* __restrict__ h_out,
    float* __restrict__ c)
{
    __shared__ __align__(16) float w_sh[2][32][32];
    __shared__ __align__(16) float x_sh[2][32][36];
    __shared__ float gate_sh[32][33];
    __shared__ int tok_sh[32];

    const int tid = threadIdx.x;
    const int jbase = blockIdx.x * 8;

    if (tid < 32) {
        int tk;
        if (mode == 0) tk = tok_src[tid * tok_stride];
        else if (mode == 1) tk = 1;  // GO token
        else {
            ull p = slots_in[tid];
            tk = (int)(0xFFFFFFFFu - (unsigned int)(p & 0xFFFFFFFFull));
            if (blockIdx.x == 0 && best_prev_out) best_prev_out[tid] = (float)tk;
        }
        tok_sh[tid] = tk;
        if (blockIdx.x == 0 && slots_reset) slots_reset[tid] = 0ull;
    }
    __syncthreads();

    // staging indices
    const int kkw = tid >> 3;            // 0..31  (W row within chunk)
    const int g   = (tid >> 1) & 3;      // gate
    const int hf  = tid & 1;             // half of 8-j group
    const int gcol = g * Hh + jbase + hf * 4;
    const int sc   = g * 8 + hf * 4;     // smem col
    const int xb = tid >> 3;             // 0..31  (batch for x staging)
    const int kq = tid & 7;              // 0..7   (k quad for x staging)
    const int mytok = tok_sh[xb];

    // compute indices
    const int col = tid & 31;            // column within 32
    const int b0  = (tid >> 5) * 4;      // batch group

    ull acc01 = 0ull, acc23 = 0ull;
    float4 wreg, xreg;

    // prologue: chunk 0
    wreg = *(const float4*)(Wx + (size_t)kkw * 4096 + gcol);
    xreg = *(const float4*)(Wo + (size_t)mytok * Dd + kq * 4);
    *(float4*)&w_sh[0][kkw][sc] = wreg;
    x_sh[0][kq*4+0][xb] = xreg.x; x_sh[0][kq*4+1][xb] = xreg.y;
    x_sh[0][kq*4+2][xb] = xreg.z; x_sh[0][kq*4+3][xb] = xreg.w;
    __syncthreads();

    int buf = 0;
    for (int ch = 0; ch < 64; ch++) {
        // prefetch next chunk into registers
        if (ch + 1 < 64) {
            int k0 = (ch + 1) * 32;
            if (k0 < 1024) {
                wreg = *(const float4*)(Wx + (size_t)(k0 + kkw) * 4096 + gcol);
                xreg = *(const float4*)(Wo + (size_t)mytok * Dd + k0 + kq * 4);
            } else {
                int kw = k0 - 1024;
                wreg = *(const float4*)(Wh + (size_t)(kw + kkw) * 4096 + gcol);
                xreg = *(const float4*)(h_in + xb * Hh + kw + kq * 4);
            }
        }
        // compute on current buffer
        #pragma unroll
        for (int kk = 0; kk < 32; kk++) {
            float w = w_sh[buf][kk][col];
            ull ww = pack2(w, w);
            float4 xv = *(const float4*)&x_sh[buf][kk][b0];
            const ull* xp = (const ull*)&xv;
            acc01 = fma2(xp[0], ww, acc01);
            acc23 = fma2(xp[1], ww, acc23);
        }
        if (ch + 1 < 64) {
            int nb = buf ^ 1;
            *(float4*)&w_sh[nb][kkw][sc] = wreg;
            x_sh[nb][kq*4+0][xb] = xreg.x; x_sh[nb][kq*4+1][xb] = xreg.y;
            x_sh[nb][kq*4+2][xb] = xreg.z; x_sh[nb][kq*4+3][xb] = xreg.w;
            __syncthreads();
            buf = nb;
        }
    }
    __syncthreads();
    gate_sh[col][b0+0] = lo2(acc01); gate_sh[col][b0+1] = hi2(acc01);
    gate_sh[col][b0+2] = lo2(acc23); gate_sh[col][b0+3] = hi2(acc23);
    __syncthreads();

    {
        int jj = tid >> 5;        // 0..7
        int b  = tid & 31;        // batch
        int J  = jbase + jj;
        float zi = gate_sh[0*8 + jj][b] + bias[J];
        float zf = gate_sh[1*8 + jj][b] + bias[Hh + J];
        float zg = gate_sh[2*8 + jj][b] + bias[2*Hh + J];
        float zo = gate_sh[3*8 + jj][b] + bias[3*Hh + J];
        float cold = c[b * Hh + J];
        float fg = 1.f / (1.f + expf(-(zf + 1.f)));   // forget_bias = 1.0
        float ig = 1.f / (1.f + expf(-zi));
        float og = 1.f / (1.f + expf(-zo));
        float cn = fg * cold + ig * tanhf(zg);
        float hn = og * tanhf(cn);
        c[b * Hh + J] = cn;
        h_out[b * Hh + J] = hn;
    }
}

// ---------------- big teacher-forced logits GEMM (FFMA2) ----------------
// C[2048,32000] = A[2048,1024] @ B[1024,32000], fp32, 128x128x8 double-buffered.
__global__ void __launch_bounds__(256, 2) gemm_logits(
    const float* __restrict__ A, const float* __restrict__ Bm, float* __restrict__ C)
{
    __shared__ __align__(16) float As[2][8][128];
    __shared__ __align__(16) float Bs[2][8][128];
    int tid = threadIdx.x;
    int nbase = blockIdx.x * 128;
    int mbase = blockIdx.y * 128;
    int tx = tid & 15, ty = tid >> 4;

    ull acc2[8][4];
    #pragma unroll
    for (int i = 0; i < 8; i++)
        #pragma unroll
        for (int jj = 0; jj < 4; jj++) acc2[i][jj] = 0ull;

    int arow = tid >> 1, akq = (tid & 1) * 4;
    int bk = tid >> 5, bnq = (tid & 31) * 4;
    const float* Aptr = A + (size_t)(mbase + arow) * 1024 + akq;
    const float* Bptr = Bm + (size_t)bk * Vv + nbase + bnq;

    {
        float4 av = *(const float4*)Aptr;
        float4 bv = *(const float4*)Bptr;
        As[0][akq+0][arow] = av.x; As[0][akq+1][arow] = av.y;
        As[0][akq+2][arow] = av.z; As[0][akq+3][arow] = av.w;
        *(float4*)&Bs[0][bk][bnq] = bv;
    }
    __syncthreads();

    int buf = 0;
    for (int k0 = 0; k0 < 1024; k0 += 8) {
        float4 av2, bv2;
        bool has = (k0 + 8) < 1024;
        if (has) {
            av2 = *(const float4*)(Aptr + (k0 + 8));
            bv2 = *(const float4*)(Bptr + (size_t)(k0 + 8) * Vv);
        }
        #pragma unroll
        for (int kk = 0; kk < 8; kk++) {
            float4 a0 = *(const float4*)&As[buf][kk][ty*8];
            float4 a1 = *(const float4*)&As[buf][kk][ty*8 + 4];
            float4 c0 = *(const float4*)&Bs[buf][kk][tx*8];
            float4 c1 = *(const float4*)&Bs[buf][kk][tx*8 + 4];
            ull bw[4];
            bw[0] = pack2(c0.x, c0.y); bw[1] = pack2(c0.z, c0.w);
            bw[2] = pack2(c1.x, c1.y); bw[3] = pack2(c1.z, c1.w);
            float ar[8] = {a0.x,a0.y,a0.z,a0.w,a1.x,a1.y,a1.z,a1.w};
            #pragma unroll
            for (int i = 0; i < 8; i++) {
                ull aw = pack2(ar[i], ar[i]);
                #pragma unroll
                for (int jj = 0; jj < 4; jj++)
                    acc2[i][jj] = fma2(bw[jj], aw, acc2[i][jj]);
            }
        }
        if (has) {
            int nb = buf ^ 1;
            As[nb][akq+0][arow] = av2.x; As[nb][akq+1][arow] = av2.y;
            As[nb][akq+2][arow] = av2.z; As[nb][akq+3][arow] = av2.w;
            *(float4*)&Bs[nb][bk][bnq] = bv2;
            __syncthreads();
            buf = nb;
        }
    }
    #pragma unroll
    for (int i = 0; i < 8; i++) {
        int row = mbase + ty * 8 + i;
        float* ptr = C + (size_t)row * Vv + nbase + tx * 8;
        float4 o0 = {lo2(acc2[i][0]), hi2(acc2[i][0]), lo2(acc2[i][1]), hi2(acc2[i][1])};
        float4 o1 = {lo2(acc2[i][2]), hi2(acc2[i][2]), lo2(acc2[i][3]), hi2(acc2[i][3])};
        *(float4*)ptr = o0;
        *(float4*)(ptr + 4) = o1;
    }
}

// ---------------- softmax over V per (t,b) row ----------------
__global__ void __launch_bounds__(256) softmax_kernel(
    const float* __restrict__ lg, float* __restrict__ pr)
{
    int row = blockIdx.x;
    const float4* src = (const float4*)(lg + (size_t)row * Vv);
    float4* dst = (float4*)(pr + (size_t)row * Vv);
    const int n4 = Vv / 4;
    int tid = threadIdx.x;

    __shared__ float red[8];
    __shared__ float s_max, s_sum;

    float m = -3.4e38f;
    for (int i = tid; i < n4; i += 256) {
        float4 v = src[i];
        m = fmaxf(m, fmaxf(fmaxf(v.x, v.y), fmaxf(v.z, v.w)));
    }
    #pragma unroll
    for (int o = 16; o; o >>= 1) m = fmaxf(m, __shfl_xor_sync(0xffffffffu, m, o));
    if ((tid & 31) == 0) red[tid >> 5] = m;
    __syncthreads();
    if (tid == 0) {
        float t = red[0];
        #pragma unroll
        for (int i = 1; i < 8; i++) t = fmaxf(t, red[i]);
        s_max = t;
    }
    __syncthreads();
    float rm = s_max;

    float s = 0.f;
    for (int i = tid; i < n4; i += 256) {
        float4 v = src[i];
        s += __expf(v.x - rm) + __expf(v.y - rm) + __expf(v.z - rm) + __expf(v.w - rm);
    }
    #pragma unroll
    for (int o = 16; o; o >>= 1) s += __shfl_xor_sync(0xffffffffu, s, o);
    if ((tid & 31) == 0) red[tid >> 5] = s;
    __syncthreads();
    if (tid == 0) {
        float t = 0.f;
        #pragma unroll
        for (int i = 0; i < 8; i++) t += red[i];
        s_sum = t;
    }
    __syncthreads();
    float inv = 1.f / s_sum;

    for (int i = tid; i < n4; i += 256) {
        float4 v = src[i];
        float4 o;
        o.x = __expf(v.x - rm) * inv; o.y = __expf(v.y - rm) * inv;
        o.z = __expf(v.z - rm) * inv; o.w = __expf(v.w - rm) * inv;
        dst[i] = o;
    }
}

// ---------------- greedy projection lg = h@Wp + block argmax (FFMA2) ----------
// grid 125 blocks x 256 cols; thread = (4 cols x 8 batches). smem-staged W + x.
__global__ void __launch_bounds__(256) proj_argmax(
    const float* __restrict__ h, const float* __restrict__ Wp,
    ull* __restrict__ slots)
{
    __shared__ __align__(16) float w_sh[2][16][256];
    __shared__ __align__(16) float x_sh[2][16][36];
    __shared__ ull wred[8][8];

    const int tid = threadIdx.x;
    const int cbase = blockIdx.x * 256;

    // staging indices
    const int kr = tid >> 6;          // 0..3  (W row base; rows kr, kr+4, kr+8, kr+12)
    const int c4 = (tid & 63) * 4;    // W col quad
    const int sb = tid >> 2;          // 0..63 (x batch; only <32 active)
    const int skq = tid & 3;          // x k-quad

    // compute indices
    const int cg = tid & 63;          // col group (4 cols)
    const int b0 = (tid >> 6) * 8;    // batch group (8 batches)

    ull acc2[4][4];
    #pragma unroll
    for (int i = 0; i < 4; i++)
        #pragma unroll
        for (int jj = 0; jj < 4; jj++) acc2[i][jj] = 0ull;

    float4 wr0, wr1, wr2, wr3, xr;

    // prologue: chunk 0
    {
        const float* wp = Wp + cbase + c4;
        wr0 = *(const float4*)(wp + (size_t)(kr     ) * Vv);
        wr1 = *(const float4*)(wp + (size_t)(kr +  4) * Vv);
        wr2 = *(const float4*)(wp + (size_t)(kr +  8) * Vv);
        wr3 = *(const float4*)(wp + (size_t)(kr + 12) * Vv);
        if (sb < 32) xr = *(const float4*)(h + sb * Hh + skq * 4);
    }
    *(float4*)&w_sh[0][kr     ][c4] = wr0;
    *(float4*)&w_sh[0][kr +  4][c4] = wr1;
    *(float4*)&w_sh[0][kr +  8][c4] = wr2;
    *(float4*)&w_sh[0][kr + 12][c4] = wr3;
    if (sb < 32) {
        x_sh[0][skq*4+0][sb] = xr.x; x_sh[0][skq*4+1][sb] = xr.y;
        x_sh[0][skq*4+2][sb] = xr.z; x_sh[0][skq*4+3][sb] = xr.w;
    }
    __syncthreads();

    int buf = 0;
    for (int ch = 0; ch < 64; ch++) {
        if (ch + 1 < 64) {
            int k0 = (ch + 1) * 16;
            const float* wp = Wp + (size_t)k0 * Vv + cbase + c4;
            wr0 = *(const float4*)(wp + (size_t)(kr     ) * Vv);
            wr1 = *(const float4*)(wp + (size_t)(kr +  4) * Vv);
            wr2 = *(const float4*)(wp + (size_t)(kr +  8) * Vv);
            wr3 = *(const float4*)(wp + (size_t)(kr + 12) * Vv);
            if (sb < 32) xr = *(const float4*)(h + sb * Hh + k0 + skq * 4);
        }
        #pragma unroll
        for (int kk = 0; kk < 16; kk++) {
            float4 w4 = *(const float4*)&w_sh[buf][kk][cg * 4];
            float4 xa = *(const float4*)&x_sh[buf][kk][b0];
            float4 xb4 = *(const float4*)&x_sh[buf][kk][b0 + 4];
            ull x01 = pack2(xa.x, xa.y),  x23 = pack2(xa.z, xa.w);
            ull x45 = pack2(xb4.x, xb4.y), x67 = pack2(xb4.z, xb4.w);
            float wf[4] = {w4.x, w4.y, w4.z, w4.w};
            #pragma unroll
            for (int cc = 0; cc < 4; cc++) {
                ull ww = pack2(wf[cc], wf[cc]);
                acc2[cc][0] = fma2(x01, ww, acc2[cc][0]);
                acc2[cc][1] = fma2(x23, ww, acc2[cc][1]);
                acc2[cc][2] = fma2(x45, ww, acc2[cc][2]);
                acc2[cc][3] = fma2(x67, ww, acc2[cc][3]);
            }
        }
        if (ch + 1 < 64) {
            int nb = buf ^ 1;
            *(float4*)&w_sh[nb][kr     ][c4] = wr0;
            *(float4*)&w_sh[nb][kr +  4][c4] = wr1;
            *(float4*)&w_sh[nb][kr +  8][c4] = wr2;
            *(float4*)&w_sh[nb][kr + 12][c4] = wr3;
            if (sb < 32) {
                x_sh[nb][skq*4+0][sb] = xr.x; x_sh[nb][skq*4+1][sb] = xr.y;
                x_sh[nb][skq*4+2][sb] = xr.z; x_sh[nb][skq*4+3][sb] = xr.w;
            }
            __syncthreads();
            buf = nb;
        }
    }

    // per-thread best over its 4 cols, for each of 8 batches; then warp reduce.
    ull pk[8];
    #pragma unroll
    for (int i = 0; i < 8; i++) {
        int p = i >> 1;
        ull best = 0ull;
        #pragma unroll
        for (int cc = 0; cc < 4; cc++) {
            float v = (i & 1) ? hi2(acc2[cc][p]) : lo2(acc2[cc][p]);
            unsigned int colg = cbase + cg * 4 + cc;
            ull pkv = ((ull)fkey(v) << 32) | (ull)(0xFFFFFFFFu - colg);
            if (pkv > best) best = pkv;
        }
        pk[i] = best;
    }
    #pragma unroll
    for (int o = 16; o; o >>= 1) {
        #pragma unroll
        for (int i = 0; i < 8; i++) {
            ull other = __shfl_xor_sync(0xffffffffu, pk[i], o);
            if (other > pk[i]) pk[i] = other;
        }
    }
    int w = tid >> 5;
    if ((tid & 31) == 0) {
        #pragma unroll
        for (int i = 0; i < 8; i++) wred[w][i] = pk[i];
    }
    __syncthreads();
    if (tid < 32) {
        int b = tid, bg = b >> 3, bi = b & 7;
        ull m0 = wred[bg * 2][bi];
        ull m1 = wred[bg * 2 + 1][bi];
        if (m1 > m0) m0 = m1;
        atomicMax(&slots[b], m0);
    }
}

__global__ void final_writer(const ull* __restrict__ slots,
                             float* __restrict__ best_out)
{
    int b = threadIdx.x;
    if (b < 32) {
        ull p = slots[b];
        best_out[b] = (float)(0xFFFFFFFFu - (unsigned int)(p & 0xFFFFFFFFull));
    }
}

// ---------------- host orchestration (graph-capturable) ----------------
extern "C" void kernel_launch(void* const* d_in, const int* in_sizes, int n_in,
                              void* d_out, int out_size)
{
    (void)in_sizes; (void)n_in; (void)out_size;
    const int*   tgt  = (const int*)d_in[0];
    const float* Wo   = (const float*)d_in[1];
    const float* Wx   = (const float*)d_in[2];
    const float* Wh   = (const float*)d_in[3];
    const float* bias = (const float*)d_in[4];
    const float* Wp   = (const float*)d_in[5];

    float* out = (float*)d_out;
    float* out_logits = out;
    float* out_probs  = out + (size_t)Tt * Bx * Vv;
    float* out_best   = out + (size_t)2 * Tt * Bx * Vv;

    float *hs, *zeros, *ctf, *cgr, *hg0, *hg1;
    ull* slots;
    cudaGetSymbolAddress((void**)&hs,    g_hs);
    cudaGetSymbolAddress((void**)&zeros, g_zeros);
    cudaGetSymbolAddress((void**)&ctf,   g_ctf);
    cudaGetSymbolAddress((void**)&cgr,   g_cgr);
    cudaGetSymbolAddress((void**)&hg0,   g_hg0);
    cudaGetSymbolAddress((void**)&hg1,   g_hg1);
    cudaGetSymbolAddress((void**)&slots, g_slots);

    init_kernel<<<(BH + 1023) / 1024, 1024>>>();

    // ---- teacher-forced scan: h_t stored into g_hs[t] ----
    for (int t = 0; t < Tt; t++) {
        lstm_cell<<<128, 256>>>(
            Wx, Wh, bias, Wo,
            tgt + t, Tt, /*mode=*/0,
            nullptr, nullptr, nullptr,
            (t == 0) ? zeros : hs + (size_t)(t - 1) * BH,
            hs + (size_t)t * BH, ctf);
    }

    // ---- logits + softmax ----
    gemm_logits<<<dim3(Vv / 128, (Tt * Bx) / 128), 256>>>(hs, Wp, out_logits);
    softmax_kernel<<<Tt * Bx, 256>>>(out_logits, out_probs);

    // ---- greedy decode ----
    for (int s = 0; s < MX; s++) {
        const float* hi = (s == 0) ? zeros : (((s - 1) & 1) ? hg1 : hg0);
        float* ho = (s & 1) ? hg1 : hg0;
        lstm_cell<<<128, 256>>>(
            Wx, Wh, bias, Wo,
            nullptr, 0, (s == 0) ? 1 : 2,
            (s == 0) ? nullptr : slots + ((s - 1) & 1) * 32,
            slots + (s & 1) * 32,
            (s == 0) ? nullptr : out_best + (size_t)(s - 1) * 32,
            hi, ho, cgr);
        proj_argmax<<<Vv / 256, 256>>>(ho, Wp, slots + (s & 1) * 32);
    }
    final_writer<<<1, 32>>>(slots + ((MX - 1) & 1) * 32,
                            out_best + (size_t)(MX - 1) * 32);
}